// round 1
// baseline (speedup 1.0000x reference)
#include <cuda_runtime.h>
#include <math.h>
#include <float.h>

#define N      16384
#define DIN    13
#define HD     16
#define KNN    8
#define JSPLIT 8

// ---- scratch (no allocs allowed) ----
__device__ float g_x[N * 16];                 // embedded points (15 mlp dims + last pfc col)
__device__ float g_sq[N];                     // squared norms
__device__ float g_pd[N * JSPLIT * KNN];      // partial top-k distances
__device__ int   g_pi[N * JSPLIT * KNN];      // partial top-k indices
__device__ int   g_idx[N * KNN];              // final knn indices

__device__ __forceinline__ float silu_f(float v) {
    return v / (1.0f + expf(-v));
}

// ============================================================
// Kernel 1: per-point MLP -> x (N x 16) and squared norms
// ============================================================
__global__ void mlp_kernel(const float* __restrict__ xp,
                           const float* __restrict__ W1, const float* __restrict__ b1,
                           const float* __restrict__ W2, const float* __restrict__ b2,
                           const float* __restrict__ W3, const float* __restrict__ b3)
{
    __shared__ float sW1[DIN * 8], sb1[8];
    __shared__ float sW2[8 * 16],  sb2[16];
    __shared__ float sW3[16 * 15], sb3[15];

    int t = threadIdx.x;
    for (int i = t; i < DIN * 8; i += blockDim.x) sW1[i] = W1[i];
    for (int i = t; i < 8;       i += blockDim.x) sb1[i] = b1[i];
    for (int i = t; i < 8 * 16;  i += blockDim.x) sW2[i] = W2[i];
    for (int i = t; i < 16;      i += blockDim.x) sb2[i] = b2[i];
    for (int i = t; i < 16 * 15; i += blockDim.x) sW3[i] = W3[i];
    for (int i = t; i < 15;      i += blockDim.x) sb3[i] = b3[i];
    __syncthreads();

    int i = blockIdx.x * blockDim.x + t;
    if (i >= N) return;

    float in[DIN];
    #pragma unroll
    for (int d = 0; d < DIN; ++d) in[d] = xp[i * DIN + d];

    float h1[8];
    #pragma unroll
    for (int h = 0; h < 8; ++h) {
        float a = sb1[h];
        #pragma unroll
        for (int d = 0; d < DIN; ++d) a = fmaf(in[d], sW1[d * 8 + h], a);
        h1[h] = silu_f(a);
    }
    float h2[16];
    #pragma unroll
    for (int h = 0; h < 16; ++h) {
        float a = sb2[h];
        #pragma unroll
        for (int d = 0; d < 8; ++d) a = fmaf(h1[d], sW2[d * 16 + h], a);
        h2[h] = silu_f(a);
    }
    float xr[16];
    #pragma unroll
    for (int h = 0; h < 15; ++h) {
        float a = sb3[h];
        #pragma unroll
        for (int d = 0; d < 16; ++d) a = fmaf(h2[d], sW3[d * 15 + h], a);
        xr[h] = a;
    }
    xr[15] = in[DIN - 1];

    float s = 0.0f;
    #pragma unroll
    for (int k = 0; k < 16; ++k) s = fmaf(xr[k], xr[k], s);

    #pragma unroll
    for (int k = 0; k < 16; ++k) g_x[i * 16 + k] = xr[k];
    g_sq[i] = s;
}

// ============================================================
// Kernel 2: fused distance + running top-8 (register blocked)
//   grid = (N/QPB) * JSPLIT CTAs, 256 threads, 4 queries/thread
// ============================================================
#define KTHREADS 256
#define IPT      4
#define QPB      (KTHREADS * IPT)   // 1024 queries per CTA
#define TJ       512                // j-tile held in shared

__global__ void __launch_bounds__(KTHREADS) knn_kernel()
{
    __shared__ float4 sx[TJ * 4];   // 512 rows x 16 floats
    __shared__ float  ssq[TJ];

    const int t       = threadIdx.x;
    const int nQGroup = N / QPB;              // 16
    const int qg      = blockIdx.x % nQGroup;
    const int sp      = blockIdx.x / nQGroup; // j-split id
    const int qbase   = qg * QPB;
    const int jbase0  = sp * (N / JSPLIT);    // 2048-wide split

    const float4* gx4 = (const float4*)g_x;

    int   q[IPT];
    float xi[IPT][16];
    float sqi[IPT];
    #pragma unroll
    for (int r = 0; r < IPT; ++r) {
        q[r] = qbase + r * KTHREADS + t;
        float4 v0 = gx4[q[r] * 4 + 0];
        float4 v1 = gx4[q[r] * 4 + 1];
        float4 v2 = gx4[q[r] * 4 + 2];
        float4 v3 = gx4[q[r] * 4 + 3];
        xi[r][0]=v0.x;  xi[r][1]=v0.y;  xi[r][2]=v0.z;  xi[r][3]=v0.w;
        xi[r][4]=v1.x;  xi[r][5]=v1.y;  xi[r][6]=v1.z;  xi[r][7]=v1.w;
        xi[r][8]=v2.x;  xi[r][9]=v2.y;  xi[r][10]=v2.z; xi[r][11]=v2.w;
        xi[r][12]=v3.x; xi[r][13]=v3.y; xi[r][14]=v3.z; xi[r][15]=v3.w;
        sqi[r] = g_sq[q[r]];
    }

    float td[IPT][KNN];
    int   ti[IPT][KNN];
    #pragma unroll
    for (int r = 0; r < IPT; ++r)
        #pragma unroll
        for (int k = 0; k < KNN; ++k) { td[r][k] = FLT_MAX; ti[r][k] = 0x7fffffff; }

    const int nTiles = (N / JSPLIT) / TJ;     // 4
    for (int jt = 0; jt < nTiles; ++jt) {
        const int jb = jbase0 + jt * TJ;
        __syncthreads();
        for (int u = t; u < TJ * 4; u += KTHREADS) sx[u] = gx4[jb * 4 + u];
        for (int u = t; u < TJ;     u += KTHREADS) ssq[u] = g_sq[jb + u];
        __syncthreads();

        for (int jj = 0; jj < TJ; ++jj) {
            // broadcast reads: whole warp reads same address -> conflict-free
            float4 a0 = sx[jj * 4 + 0];
            float4 a1 = sx[jj * 4 + 1];
            float4 a2 = sx[jj * 4 + 2];
            float4 a3 = sx[jj * 4 + 3];
            float  sqj = ssq[jj];
            int    j   = jb + jj;

            #pragma unroll
            for (int r = 0; r < IPT; ++r) {
                // two fma chains for ILP
                float e0 = xi[r][0] * a0.x;
                e0 = fmaf(xi[r][1],  a0.y, e0);
                e0 = fmaf(xi[r][2],  a0.z, e0);
                e0 = fmaf(xi[r][3],  a0.w, e0);
                e0 = fmaf(xi[r][4],  a1.x, e0);
                e0 = fmaf(xi[r][5],  a1.y, e0);
                e0 = fmaf(xi[r][6],  a1.z, e0);
                e0 = fmaf(xi[r][7],  a1.w, e0);
                float e1 = xi[r][8] * a2.x;
                e1 = fmaf(xi[r][9],  a2.y, e1);
                e1 = fmaf(xi[r][10], a2.z, e1);
                e1 = fmaf(xi[r][11], a2.w, e1);
                e1 = fmaf(xi[r][12], a3.x, e1);
                e1 = fmaf(xi[r][13], a3.y, e1);
                e1 = fmaf(xi[r][14], a3.z, e1);
                e1 = fmaf(xi[r][15], a3.w, e1);
                float dot = e0 + e1;
                float d2  = fmaf(-2.0f, dot, sqj) + sqi[r];

                if (d2 < td[r][KNN - 1]) {
                    td[r][KNN - 1] = d2;
                    ti[r][KNN - 1] = j;
                    #pragma unroll
                    for (int s = KNN - 1; s >= 1; --s) {
                        if (td[r][s] < td[r][s - 1]) {
                            float tf = td[r][s]; td[r][s] = td[r][s - 1]; td[r][s - 1] = tf;
                            int   tn = ti[r][s]; ti[r][s] = ti[r][s - 1]; ti[r][s - 1] = tn;
                        }
                    }
                }
            }
        }
    }

    #pragma unroll
    for (int r = 0; r < IPT; ++r) {
        int base = (q[r] * JSPLIT + sp) * KNN;
        #pragma unroll
        for (int k = 0; k < KNN; ++k) {
            g_pd[base + k] = td[r][k];
            g_pi[base + k] = ti[r][k];
        }
    }
}

// ============================================================
// Kernel 3: merge JSPLIT partial top-8 lists -> final indices
// ============================================================
__global__ void merge_kernel()
{
    int i = blockIdx.x * blockDim.x + threadIdx.x;
    if (i >= N) return;

    float d[JSPLIT * KNN];
    int   ix[JSPLIT * KNN];
    #pragma unroll
    for (int u = 0; u < JSPLIT * KNN; ++u) {
        d[u]  = g_pd[i * JSPLIT * KNN + u];
        ix[u] = g_pi[i * JSPLIT * KNN + u];
    }
    for (int k = 0; k < KNN; ++k) {
        float bd = FLT_MAX; int bi = 0x7fffffff; int bu = 0;
        for (int u = 0; u < JSPLIT * KNN; ++u) {
            if (d[u] < bd || (d[u] == bd && ix[u] < bi)) {
                bd = d[u]; bi = ix[u]; bu = u;
            }
        }
        g_idx[i * KNN + k] = bi;
        d[bu] = FLT_MAX; ix[bu] = 0x7fffffff;
    }
}

// ============================================================
// Kernel 4: edge messages + mean + final MLP + concat output
// ============================================================
__global__ void edge_kernel(const float* __restrict__ xp,
                            const float* __restrict__ We,  const float* __restrict__ be,
                            const float* __restrict__ Wf1, const float* __restrict__ bf1,
                            const float* __restrict__ Wf2, const float* __restrict__ bf2,
                            float* __restrict__ out)
{
    __shared__ float sWd[16 * 16];   // We_top - We_bot  (applied to x_i)
    __shared__ float sWb[16 * 16];   // We_bot           (applied to x_j)
    __shared__ float sbe[16];
    __shared__ float sWf1[16 * 32], sbf1[32];
    __shared__ float sWf2[32 * 16], sbf2[16];

    int t = threadIdx.x;
    for (int u = t; u < 256; u += blockDim.x) {
        float top = We[u];            // rows 0..15
        float bot = We[256 + u];      // rows 16..31
        sWd[u] = top - bot;
        sWb[u] = bot;
    }
    for (int u = t; u < 16;      u += blockDim.x) sbe[u]  = be[u];
    for (int u = t; u < 16 * 32; u += blockDim.x) sWf1[u] = Wf1[u];
    for (int u = t; u < 32;      u += blockDim.x) sbf1[u] = bf1[u];
    for (int u = t; u < 32 * 16; u += blockDim.x) sWf2[u] = Wf2[u];
    for (int u = t; u < 16;      u += blockDim.x) sbf2[u] = bf2[u];
    __syncthreads();

    int i = blockIdx.x * blockDim.x + t;
    if (i >= N) return;

    const float4* gx4 = (const float4*)g_x;
    float xi[16];
    {
        float4 v0 = gx4[i * 4 + 0], v1 = gx4[i * 4 + 1];
        float4 v2 = gx4[i * 4 + 2], v3 = gx4[i * 4 + 3];
        xi[0]=v0.x;  xi[1]=v0.y;  xi[2]=v0.z;  xi[3]=v0.w;
        xi[4]=v1.x;  xi[5]=v1.y;  xi[6]=v1.z;  xi[7]=v1.w;
        xi[8]=v2.x;  xi[9]=v2.y;  xi[10]=v2.z; xi[11]=v2.w;
        xi[12]=v3.x; xi[13]=v3.y; xi[14]=v3.z; xi[15]=v3.w;
    }

    // pre[h] = be[h] + x_i . (We_top - We_bot)
    float pre[16];
    #pragma unroll
    for (int h = 0; h < 16; ++h) {
        float a = sbe[h];
        #pragma unroll
        for (int d = 0; d < 16; ++d) a = fmaf(xi[d], sWd[d * 16 + h], a);
        pre[h] = a;
    }

    float fsum[16];
    #pragma unroll
    for (int h = 0; h < 16; ++h) fsum[h] = 0.0f;

    #pragma unroll
    for (int k = 0; k < KNN; ++k) {
        int j = g_idx[i * KNN + k];
        float xj[16];
        float4 v0 = gx4[j * 4 + 0], v1 = gx4[j * 4 + 1];
        float4 v2 = gx4[j * 4 + 2], v3 = gx4[j * 4 + 3];
        xj[0]=v0.x;  xj[1]=v0.y;  xj[2]=v0.z;  xj[3]=v0.w;
        xj[4]=v1.x;  xj[5]=v1.y;  xj[6]=v1.z;  xj[7]=v1.w;
        xj[8]=v2.x;  xj[9]=v2.y;  xj[10]=v2.z; xj[11]=v2.w;
        xj[12]=v3.x; xj[13]=v3.y; xj[14]=v3.z; xj[15]=v3.w;

        #pragma unroll
        for (int h = 0; h < 16; ++h) {
            float m = pre[h];
            #pragma unroll
            for (int d = 0; d < 16; ++d) m = fmaf(xj[d], sWb[d * 16 + h], m);
            fsum[h] += silu_f(m);
        }
    }

    float feats[16];
    #pragma unroll
    for (int h = 0; h < 16; ++h) feats[h] = fsum[h] * 0.125f;

    float f1[32];
    #pragma unroll
    for (int h = 0; h < 32; ++h) {
        float a = sbf1[h];
        #pragma unroll
        for (int d = 0; d < 16; ++d) a = fmaf(feats[d], sWf1[d * 32 + h], a);
        f1[h] = silu_f(a);
    }
    float f2[16];
    #pragma unroll
    for (int h = 0; h < 16; ++h) {
        float a = sbf2[h];
        #pragma unroll
        for (int d = 0; d < 32; ++d) a = fmaf(f1[d], sWf2[d * 16 + h], a);
        f2[h] = a;
    }

    float* o = out + i * (16 + DIN);
    #pragma unroll
    for (int h = 0; h < 16; ++h) o[h] = f2[h];
    #pragma unroll
    for (int d = 0; d < DIN; ++d) o[16 + d] = xp[i * DIN + d];
}

// ============================================================
extern "C" void kernel_launch(void* const* d_in, const int* in_sizes, int n_in,
                              void* d_out, int out_size)
{
    const float* xp  = (const float*)d_in[0];
    const float* W1  = (const float*)d_in[1];
    const float* b1  = (const float*)d_in[2];
    const float* W2  = (const float*)d_in[3];
    const float* b2  = (const float*)d_in[4];
    const float* W3  = (const float*)d_in[5];
    const float* b3  = (const float*)d_in[6];
    const float* We  = (const float*)d_in[7];
    const float* be  = (const float*)d_in[8];
    const float* Wf1 = (const float*)d_in[9];
    const float* bf1 = (const float*)d_in[10];
    const float* Wf2 = (const float*)d_in[11];
    const float* bf2 = (const float*)d_in[12];
    float* out = (float*)d_out;

    mlp_kernel<<<N / 256, 256>>>(xp, W1, b1, W2, b2, W3, b3);
    knn_kernel<<<(N / QPB) * JSPLIT, KTHREADS>>>();
    merge_kernel<<<N / 256, 256>>>();
    edge_kernel<<<N / 256, 256>>>(xp, We, be, Wf1, bf1, Wf2, bf2, out);
}

// round 2
// speedup vs baseline: 1.0613x; 1.0613x over previous
#include <cuda_runtime.h>
#include <math.h>
#include <float.h>

#define N      16384
#define DIN    13
#define KNN    8
#define JSPLIT 8

typedef unsigned long long ull;

// ---- scratch (no allocs allowed) ----
__device__ float g_x[N * 16];                 // embedded points
__device__ float g_sq[N];                     // squared norms
__device__ float g_pd[N * JSPLIT * KNN];      // partial top-k "distances" (d2 - sq_i)
__device__ int   g_pi[N * JSPLIT * KNN];      // partial top-k indices
__device__ int   g_idx[N * KNN];              // final knn indices

__device__ __forceinline__ float silu_f(float v) {
    return v / (1.0f + expf(-v));
}
__device__ __forceinline__ float silu_fast(float v) {
    return __fdividef(v, 1.0f + __expf(-v));
}

// ---- packed f32x2 helpers (sm_100+) ----
__device__ __forceinline__ ull pack2(float lo, float hi) {
    ull p; asm("mov.b64 %0, {%1, %2};" : "=l"(p) : "f"(lo), "f"(hi)); return p;
}
__device__ __forceinline__ ull fma2(ull a, ull b, ull c) {
    ull d; asm("fma.rn.f32x2 %0, %1, %2, %3;" : "=l"(d) : "l"(a), "l"(b), "l"(c)); return d;
}
__device__ __forceinline__ ull mul2(ull a, ull b) {
    ull d; asm("mul.rn.f32x2 %0, %1, %2;" : "=l"(d) : "l"(a), "l"(b)); return d;
}
__device__ __forceinline__ ull add2(ull a, ull b) {
    ull d; asm("add.rn.f32x2 %0, %1, %2;" : "=l"(d) : "l"(a), "l"(b)); return d;
}
__device__ __forceinline__ float hsum2(ull s) {
    float lo, hi; asm("mov.b64 {%0, %1}, %2;" : "=f"(lo), "=f"(hi) : "l"(s));
    return lo + hi;
}

// ============================================================
// Kernel 1: per-point MLP -> x (N x 16) and squared norms
// ============================================================
__global__ void mlp_kernel(const float* __restrict__ xp,
                           const float* __restrict__ W1, const float* __restrict__ b1,
                           const float* __restrict__ W2, const float* __restrict__ b2,
                           const float* __restrict__ W3, const float* __restrict__ b3)
{
    __shared__ float sW1[DIN * 8], sb1[8];
    __shared__ float sW2[8 * 16],  sb2[16];
    __shared__ float sW3[16 * 15], sb3[15];

    int t = threadIdx.x;
    for (int i = t; i < DIN * 8; i += blockDim.x) sW1[i] = W1[i];
    for (int i = t; i < 8;       i += blockDim.x) sb1[i] = b1[i];
    for (int i = t; i < 8 * 16;  i += blockDim.x) sW2[i] = W2[i];
    for (int i = t; i < 16;      i += blockDim.x) sb2[i] = b2[i];
    for (int i = t; i < 16 * 15; i += blockDim.x) sW3[i] = W3[i];
    for (int i = t; i < 15;      i += blockDim.x) sb3[i] = b3[i];
    __syncthreads();

    int i = blockIdx.x * blockDim.x + t;
    if (i >= N) return;

    float in[DIN];
    #pragma unroll
    for (int d = 0; d < DIN; ++d) in[d] = xp[i * DIN + d];

    float h1[8];
    #pragma unroll
    for (int h = 0; h < 8; ++h) {
        float a = sb1[h];
        #pragma unroll
        for (int d = 0; d < DIN; ++d) a = fmaf(in[d], sW1[d * 8 + h], a);
        h1[h] = silu_f(a);
    }
    float h2[16];
    #pragma unroll
    for (int h = 0; h < 16; ++h) {
        float a = sb2[h];
        #pragma unroll
        for (int d = 0; d < 8; ++d) a = fmaf(h1[d], sW2[d * 16 + h], a);
        h2[h] = silu_f(a);
    }
    float xr[16];
    #pragma unroll
    for (int h = 0; h < 15; ++h) {
        float a = sb3[h];
        #pragma unroll
        for (int d = 0; d < 16; ++d) a = fmaf(h2[d], sW3[d * 15 + h], a);
        xr[h] = a;
    }
    xr[15] = in[DIN - 1];

    float s = 0.0f;
    #pragma unroll
    for (int k = 0; k < 16; ++k) s = fmaf(xr[k], xr[k], s);

    #pragma unroll
    for (int k = 0; k < 16; ++k) g_x[i * 16 + k] = xr[k];
    g_sq[i] = s;
}

// ============================================================
// Kernel 2: fused distance + running top-8, packed f32x2 math
// ============================================================
#define KTHREADS 256
#define IPT      4
#define QPB      (KTHREADS * IPT)   // 1024 queries per CTA
#define TJ       512                // j-tile held in shared

__global__ void __launch_bounds__(KTHREADS) knn_kernel()
{
    __shared__ ulonglong2 sx2[TJ * 4];   // 512 rows x 16 floats (as 8 packed pairs)
    __shared__ ull        ssq2[TJ];      // (sq_j, 0) packed

    const int t       = threadIdx.x;
    const int nQGroup = N / QPB;              // 16
    const int qg      = blockIdx.x % nQGroup;
    const int sp      = blockIdx.x / nQGroup; // j-split id
    const int qbase   = qg * QPB;
    const int jbase0  = sp * (N / JSPLIT);    // 2048-wide split

    const ulonglong2* gx2 = (const ulonglong2*)g_x;

    // query vectors: xi2 = -2 * x_i, packed into 8 f32x2 per query
    int q[IPT];
    ull xi2[IPT][8];
    #pragma unroll
    for (int r = 0; r < IPT; ++r) {
        q[r] = qbase + r * KTHREADS + t;
        const float* xr = g_x + q[r] * 16;
        #pragma unroll
        for (int p = 0; p < 8; ++p)
            xi2[r][p] = pack2(-2.0f * xr[2 * p], -2.0f * xr[2 * p + 1]);
    }

    float td[IPT][KNN];
    int   ti[IPT][KNN];
    #pragma unroll
    for (int r = 0; r < IPT; ++r)
        #pragma unroll
        for (int k = 0; k < KNN; ++k) { td[r][k] = FLT_MAX; ti[r][k] = 0x7fffffff; }

    const int nTiles = (N / JSPLIT) / TJ;     // 4
    for (int jt = 0; jt < nTiles; ++jt) {
        const int jb = jbase0 + jt * TJ;
        __syncthreads();
        for (int u = t; u < TJ * 4; u += KTHREADS) sx2[u] = gx2[jb * 4 + u];
        for (int u = t; u < TJ;     u += KTHREADS) ssq2[u] = pack2(g_sq[jb + u], 0.0f);
        __syncthreads();

        for (int jj = 0; jj < TJ; ++jj) {
            // broadcast reads: whole warp reads same address -> conflict-free
            ulonglong2 p0 = sx2[jj * 4 + 0];
            ulonglong2 p1 = sx2[jj * 4 + 1];
            ulonglong2 p2 = sx2[jj * 4 + 2];
            ulonglong2 p3 = sx2[jj * 4 + 3];
            ull sq2 = ssq2[jj];

            #pragma unroll
            for (int r = 0; r < IPT; ++r) {
                // d2' = sq_j - 2 * dot(x_i, x_j)   (sq_i dropped: per-query constant)
                ull a = fma2(xi2[r][0], p0.x, sq2);
                a = fma2(xi2[r][1], p0.y, a);
                a = fma2(xi2[r][2], p1.x, a);
                a = fma2(xi2[r][3], p1.y, a);
                ull b = mul2(xi2[r][4], p2.x);
                b = fma2(xi2[r][5], p2.y, b);
                b = fma2(xi2[r][6], p3.x, b);
                b = fma2(xi2[r][7], p3.y, b);
                float d2 = hsum2(add2(a, b));

                if (d2 < td[r][KNN - 1]) {
                    td[r][KNN - 1] = d2;
                    ti[r][KNN - 1] = jb + jj;
                    #pragma unroll
                    for (int s = KNN - 1; s >= 1; --s) {
                        if (td[r][s] < td[r][s - 1]) {
                            float tf = td[r][s]; td[r][s] = td[r][s - 1]; td[r][s - 1] = tf;
                            int   tn = ti[r][s]; ti[r][s] = ti[r][s - 1]; ti[r][s - 1] = tn;
                        }
                    }
                }
            }
        }
    }

    #pragma unroll
    for (int r = 0; r < IPT; ++r) {
        int base = (q[r] * JSPLIT + sp) * KNN;
        #pragma unroll
        for (int k = 0; k < KNN; ++k) {
            g_pd[base + k] = td[r][k];
            g_pi[base + k] = ti[r][k];
        }
    }
}

// ============================================================
// Kernel 3: merge JSPLIT partial top-8 lists -> final indices
// ============================================================
__global__ void merge_kernel()
{
    int i = blockIdx.x * blockDim.x + threadIdx.x;
    if (i >= N) return;

    float d[JSPLIT * KNN];
    int   ix[JSPLIT * KNN];
    #pragma unroll
    for (int u = 0; u < JSPLIT * KNN; ++u) {
        d[u]  = g_pd[i * JSPLIT * KNN + u];
        ix[u] = g_pi[i * JSPLIT * KNN + u];
    }
    for (int k = 0; k < KNN; ++k) {
        float bd = FLT_MAX; int bi = 0x7fffffff; int bu = 0;
        for (int u = 0; u < JSPLIT * KNN; ++u) {
            if (d[u] < bd || (d[u] == bd && ix[u] < bi)) {
                bd = d[u]; bi = ix[u]; bu = u;
            }
        }
        g_idx[i * KNN + k] = bi;
        d[bu] = FLT_MAX; ix[bu] = 0x7fffffff;
    }
}

// ============================================================
// Kernel 4: edge messages + mean + final MLP + concat output
// ============================================================
#define ETHREADS 128

__global__ void __launch_bounds__(ETHREADS)
edge_kernel(const float* __restrict__ xp,
            const float* __restrict__ We,  const float* __restrict__ be,
            const float* __restrict__ Wf1, const float* __restrict__ bf1,
            const float* __restrict__ Wf2, const float* __restrict__ bf2,
            float* __restrict__ out)
{
    __shared__ float sWd[16 * 16];   // We_top - We_bot  (applied to x_i)
    __shared__ float sWb[16 * 16];   // We_bot           (applied to x_j)
    __shared__ float sbe[16];
    __shared__ float sWf1[16 * 32], sbf1[32];
    __shared__ float sWf2[32 * 16], sbf2[16];

    int t = threadIdx.x;
    for (int u = t; u < 256; u += ETHREADS) {
        float top = We[u];            // rows 0..15
        float bot = We[256 + u];      // rows 16..31
        sWd[u] = top - bot;
        sWb[u] = bot;
    }
    for (int u = t; u < 16;      u += ETHREADS) sbe[u]  = be[u];
    for (int u = t; u < 16 * 32; u += ETHREADS) sWf1[u] = Wf1[u];
    for (int u = t; u < 32;      u += ETHREADS) sbf1[u] = bf1[u];
    for (int u = t; u < 32 * 16; u += ETHREADS) sWf2[u] = Wf2[u];
    for (int u = t; u < 16;      u += ETHREADS) sbf2[u] = bf2[u];
    __syncthreads();

    int i = blockIdx.x * ETHREADS + t;
    if (i >= N) return;

    const float4* gx4 = (const float4*)g_x;
    float xi[16];
    {
        float4 v0 = gx4[i * 4 + 0], v1 = gx4[i * 4 + 1];
        float4 v2 = gx4[i * 4 + 2], v3 = gx4[i * 4 + 3];
        xi[0]=v0.x;  xi[1]=v0.y;  xi[2]=v0.z;  xi[3]=v0.w;
        xi[4]=v1.x;  xi[5]=v1.y;  xi[6]=v1.z;  xi[7]=v1.w;
        xi[8]=v2.x;  xi[9]=v2.y;  xi[10]=v2.z; xi[11]=v2.w;
        xi[12]=v3.x; xi[13]=v3.y; xi[14]=v3.z; xi[15]=v3.w;
    }

    // pre[h] = be[h] + x_i . (We_top - We_bot)
    float pre[16];
    #pragma unroll
    for (int h = 0; h < 16; ++h) {
        float a = sbe[h];
        #pragma unroll
        for (int d = 0; d < 16; ++d) a = fmaf(xi[d], sWd[d * 16 + h], a);
        pre[h] = a;
    }

    float fsum[16];
    #pragma unroll
    for (int h = 0; h < 16; ++h) fsum[h] = 0.0f;

    #pragma unroll
    for (int k = 0; k < KNN; ++k) {
        int j = g_idx[i * KNN + k];
        float xj[16];
        float4 v0 = gx4[j * 4 + 0], v1 = gx4[j * 4 + 1];
        float4 v2 = gx4[j * 4 + 2], v3 = gx4[j * 4 + 3];
        xj[0]=v0.x;  xj[1]=v0.y;  xj[2]=v0.z;  xj[3]=v0.w;
        xj[4]=v1.x;  xj[5]=v1.y;  xj[6]=v1.z;  xj[7]=v1.w;
        xj[8]=v2.x;  xj[9]=v2.y;  xj[10]=v2.z; xj[11]=v2.w;
        xj[12]=v3.x; xj[13]=v3.y; xj[14]=v3.z; xj[15]=v3.w;

        #pragma unroll
        for (int h = 0; h < 16; ++h) {
            float m = pre[h];
            #pragma unroll
            for (int d = 0; d < 16; ++d) m = fmaf(xj[d], sWb[d * 16 + h], m);
            fsum[h] += silu_fast(m);
        }
    }

    float feats[16];
    #pragma unroll
    for (int h = 0; h < 16; ++h) feats[h] = fsum[h] * 0.125f;

    float f1[32];
    #pragma unroll
    for (int h = 0; h < 32; ++h) {
        float a = sbf1[h];
        #pragma unroll
        for (int d = 0; d < 16; ++d) a = fmaf(feats[d], sWf1[d * 32 + h], a);
        f1[h] = silu_fast(a);
    }
    float f2[16];
    #pragma unroll
    for (int h = 0; h < 16; ++h) {
        float a = sbf2[h];
        #pragma unroll
        for (int d = 0; d < 32; ++d) a = fmaf(f1[d], sWf2[d * 16 + h], a);
        f2[h] = a;
    }

    float* o = out + i * (16 + DIN);
    #pragma unroll
    for (int h = 0; h < 16; ++h) o[h] = f2[h];
    #pragma unroll
    for (int d = 0; d < DIN; ++d) o[16 + d] = xp[i * DIN + d];
}

// ============================================================
extern "C" void kernel_launch(void* const* d_in, const int* in_sizes, int n_in,
                              void* d_out, int out_size)
{
    const float* xp  = (const float*)d_in[0];
    const float* W1  = (const float*)d_in[1];
    const float* b1  = (const float*)d_in[2];
    const float* W2  = (const float*)d_in[3];
    const float* b2  = (const float*)d_in[4];
    const float* W3  = (const float*)d_in[5];
    const float* b3  = (const float*)d_in[6];
    const float* We  = (const float*)d_in[7];
    const float* be  = (const float*)d_in[8];
    const float* Wf1 = (const float*)d_in[9];
    const float* bf1 = (const float*)d_in[10];
    const float* Wf2 = (const float*)d_in[11];
    const float* bf2 = (const float*)d_in[12];
    float* out = (float*)d_out;

    mlp_kernel<<<N / 256, 256>>>(xp, W1, b1, W2, b2, W3, b3);
    knn_kernel<<<(N / QPB) * JSPLIT, KTHREADS>>>();
    merge_kernel<<<N / 256, 256>>>();
    edge_kernel<<<N / ETHREADS, ETHREADS>>>(xp, We, be, Wf1, bf1, Wf2, bf2, out);
}

// round 3
// speedup vs baseline: 1.2848x; 1.2106x over previous
#include <cuda_runtime.h>
#include <math.h>
#include <float.h>

#define N      16384
#define DIN    13
#define KNN    8
#define JSPLIT 8

typedef unsigned long long ull;

// ---- scratch (no allocs allowed) ----
__device__ float g_x[N * 16];                 // embedded points
__device__ float g_sq[N];                     // squared norms
__device__ float g_pd[N * JSPLIT * KNN];      // partial top-k surrogate distances (d2 - sq_i)
__device__ int   g_pi[N * JSPLIT * KNN];      // partial top-k indices
__device__ int   g_idx[N * KNN];              // final knn indices
__device__ float g_feats[N * 16];             // mean edge messages

__device__ __forceinline__ float silu_f(float v) {
    return v / (1.0f + expf(-v));
}
__device__ __forceinline__ float silu_fast(float v) {
    return __fdividef(v, 1.0f + __expf(-v));
}

// ---- packed f32x2 helpers (sm_100+) ----
__device__ __forceinline__ ull pack2(float lo, float hi) {
    ull p; asm("mov.b64 %0, {%1, %2};" : "=l"(p) : "f"(lo), "f"(hi)); return p;
}
__device__ __forceinline__ ull fma2(ull a, ull b, ull c) {
    ull d; asm("fma.rn.f32x2 %0, %1, %2, %3;" : "=l"(d) : "l"(a), "l"(b), "l"(c)); return d;
}
__device__ __forceinline__ ull mul2(ull a, ull b) {
    ull d; asm("mul.rn.f32x2 %0, %1, %2;" : "=l"(d) : "l"(a), "l"(b)); return d;
}
__device__ __forceinline__ ull add2(ull a, ull b) {
    ull d; asm("add.rn.f32x2 %0, %1, %2;" : "=l"(d) : "l"(a), "l"(b)); return d;
}
__device__ __forceinline__ void unpack2(ull s, float& lo, float& hi) {
    asm("mov.b64 {%0, %1}, %2;" : "=f"(lo), "=f"(hi) : "l"(s));
}

// ============================================================
// Kernel 1: per-point MLP -> x (N x 16) and squared norms
// ============================================================
__global__ void mlp_kernel(const float* __restrict__ xp,
                           const float* __restrict__ W1, const float* __restrict__ b1,
                           const float* __restrict__ W2, const float* __restrict__ b2,
                           const float* __restrict__ W3, const float* __restrict__ b3)
{
    __shared__ float sW1[DIN * 8], sb1[8];
    __shared__ float sW2[8 * 16],  sb2[16];
    __shared__ float sW3[16 * 15], sb3[15];

    int t = threadIdx.x;
    for (int i = t; i < DIN * 8; i += blockDim.x) sW1[i] = W1[i];
    for (int i = t; i < 8;       i += blockDim.x) sb1[i] = b1[i];
    for (int i = t; i < 8 * 16;  i += blockDim.x) sW2[i] = W2[i];
    for (int i = t; i < 16;      i += blockDim.x) sb2[i] = b2[i];
    for (int i = t; i < 16 * 15; i += blockDim.x) sW3[i] = W3[i];
    for (int i = t; i < 15;      i += blockDim.x) sb3[i] = b3[i];
    __syncthreads();

    int i = blockIdx.x * blockDim.x + t;
    if (i >= N) return;

    float in[DIN];
    #pragma unroll
    for (int d = 0; d < DIN; ++d) in[d] = xp[i * DIN + d];

    float h1[8];
    #pragma unroll
    for (int h = 0; h < 8; ++h) {
        float a = sb1[h];
        #pragma unroll
        for (int d = 0; d < DIN; ++d) a = fmaf(in[d], sW1[d * 8 + h], a);
        h1[h] = silu_f(a);
    }
    float h2[16];
    #pragma unroll
    for (int h = 0; h < 16; ++h) {
        float a = sb2[h];
        #pragma unroll
        for (int d = 0; d < 8; ++d) a = fmaf(h1[d], sW2[d * 16 + h], a);
        h2[h] = silu_f(a);
    }
    float xr[16];
    #pragma unroll
    for (int h = 0; h < 15; ++h) {
        float a = sb3[h];
        #pragma unroll
        for (int d = 0; d < 16; ++d) a = fmaf(h2[d], sW3[d * 15 + h], a);
        xr[h] = a;
    }
    xr[15] = in[DIN - 1];

    float s = 0.0f;
    #pragma unroll
    for (int k = 0; k < 16; ++k) s = fmaf(xr[k], xr[k], s);

    #pragma unroll
    for (int k = 0; k < 16; ++k) g_x[i * 16 + k] = xr[k];
    g_sq[i] = s;
}

// ============================================================
// Kernel 2: fused distance + running top-8
//   j-pair-per-lane f32x2: one 16-FMA2 chain = two full d2 values
// ============================================================
#define KTHREADS 128
#define IPT      2
#define QPB      (KTHREADS * IPT)   // 256 queries per CTA
#define TJ       512                // j-tile in shared
#define JP       (TJ / 2)           // 256 j-pairs

__global__ void __launch_bounds__(KTHREADS, 3) knn_kernel()
{
    __shared__ ulonglong2 sxp2[JP * 8];  // 256 pairs x 16 dims (lane0=j even, lane1=j odd)
    __shared__ ull        ssq2[JP];      // (sq_j0, sq_j1)

    const int t       = threadIdx.x;
    const int nQGroup = N / QPB;              // 64
    const int qg      = blockIdx.x % nQGroup;
    const int sp      = blockIdx.x / nQGroup; // j-split id
    const int qbase   = qg * QPB;
    const int jbase0  = sp * (N / JSPLIT);    // 2048-wide split

    // queries: both lanes hold -2*x_i[d]
    int q[IPT];
    ull xi2[IPT][16];
    #pragma unroll
    for (int r = 0; r < IPT; ++r) {
        q[r] = qbase + r * KTHREADS + t;
        const float* xr = g_x + q[r] * 16;
        #pragma unroll
        for (int d = 0; d < 16; ++d) {
            float v = -2.0f * xr[d];
            xi2[r][d] = pack2(v, v);
        }
    }

    float td[IPT][KNN];
    int   ti[IPT][KNN];
    #pragma unroll
    for (int r = 0; r < IPT; ++r)
        #pragma unroll
        for (int k = 0; k < KNN; ++k) { td[r][k] = FLT_MAX; ti[r][k] = 0x7fffffff; }

    ull* sview = (ull*)sxp2;
    const int nTiles = (N / JSPLIT) / TJ;     // 4
    for (int jt = 0; jt < nTiles; ++jt) {
        const int jb = jbase0 + jt * TJ;
        __syncthreads();
        // build pair-interleaved tile
        for (int u = t; u < JP * 16; u += KTHREADS) {
            int jp = u >> 4, d = u & 15;
            const float* p = g_x + (jb + 2 * jp) * 16 + d;
            sview[u] = pack2(p[0], p[16]);
        }
        for (int u = t; u < JP; u += KTHREADS)
            ssq2[u] = pack2(g_sq[jb + 2 * u], g_sq[jb + 2 * u + 1]);
        __syncthreads();

        for (int jp = 0; jp < JP; ++jp) {
            // broadcast reads (all threads read same address)
            const ulonglong2* vp = sxp2 + jp * 8;
            ulonglong2 v0 = vp[0], v1 = vp[1], v2 = vp[2], v3 = vp[3];
            ulonglong2 v4 = vp[4], v5 = vp[5], v6 = vp[6], v7 = vp[7];
            ull s2 = ssq2[jp];
            int j0 = jb + 2 * jp;

            #pragma unroll
            for (int r = 0; r < IPT; ++r) {
                // lane L: d2' = sq_jL - 2*dot(x_i, x_jL)  (sq_i dropped: monotone shift)
                ull a = fma2(xi2[r][0],  v0.x, s2);
                a = fma2(xi2[r][1],  v0.y, a);
                a = fma2(xi2[r][2],  v1.x, a);
                a = fma2(xi2[r][3],  v1.y, a);
                a = fma2(xi2[r][4],  v2.x, a);
                a = fma2(xi2[r][5],  v2.y, a);
                a = fma2(xi2[r][6],  v3.x, a);
                a = fma2(xi2[r][7],  v3.y, a);
                ull b = mul2(xi2[r][8],  v4.x);
                b = fma2(xi2[r][9],  v4.y, b);
                b = fma2(xi2[r][10], v5.x, b);
                b = fma2(xi2[r][11], v5.y, b);
                b = fma2(xi2[r][12], v6.x, b);
                b = fma2(xi2[r][13], v6.y, b);
                b = fma2(xi2[r][14], v7.x, b);
                b = fma2(xi2[r][15], v7.y, b);
                ull acc = add2(a, b);
                float d0, d1;
                unpack2(acc, d0, d1);

                if (fminf(d0, d1) < td[r][KNN - 1]) {
                    // sequential semantics: lower j first, strict <
                    if (d0 < td[r][KNN - 1]) {
                        td[r][KNN - 1] = d0; ti[r][KNN - 1] = j0;
                        #pragma unroll
                        for (int s = KNN - 1; s >= 1; --s)
                            if (td[r][s] < td[r][s - 1]) {
                                float tf = td[r][s]; td[r][s] = td[r][s-1]; td[r][s-1] = tf;
                                int   tn = ti[r][s]; ti[r][s] = ti[r][s-1]; ti[r][s-1] = tn;
                            }
                    }
                    if (d1 < td[r][KNN - 1]) {
                        td[r][KNN - 1] = d1; ti[r][KNN - 1] = j0 + 1;
                        #pragma unroll
                        for (int s = KNN - 1; s >= 1; --s)
                            if (td[r][s] < td[r][s - 1]) {
                                float tf = td[r][s]; td[r][s] = td[r][s-1]; td[r][s-1] = tf;
                                int   tn = ti[r][s]; ti[r][s] = ti[r][s-1]; ti[r][s-1] = tn;
                            }
                    }
                }
            }
        }
    }

    #pragma unroll
    for (int r = 0; r < IPT; ++r) {
        int base = (q[r] * JSPLIT + sp) * KNN;
        #pragma unroll
        for (int k = 0; k < KNN; ++k) {
            g_pd[base + k] = td[r][k];
            g_pi[base + k] = ti[r][k];
        }
    }
}

// ============================================================
// Kernel 3: merge JSPLIT partial top-8 lists -> final indices
// ============================================================
__global__ void merge_kernel()
{
    int i = blockIdx.x * blockDim.x + threadIdx.x;
    if (i >= N) return;

    float d[JSPLIT * KNN];
    int   ix[JSPLIT * KNN];
    #pragma unroll
    for (int u = 0; u < JSPLIT * KNN; ++u) {
        d[u]  = g_pd[i * JSPLIT * KNN + u];
        ix[u] = g_pi[i * JSPLIT * KNN + u];
    }
    for (int k = 0; k < KNN; ++k) {
        float bd = FLT_MAX; int bi = 0x7fffffff; int bu = 0;
        for (int u = 0; u < JSPLIT * KNN; ++u) {
            if (d[u] < bd || (d[u] == bd && ix[u] < bi)) {
                bd = d[u]; bi = ix[u]; bu = u;
            }
        }
        g_idx[i * KNN + k] = bi;
        d[bu] = FLT_MAX; ix[bu] = 0x7fffffff;
    }
}

// ============================================================
// Kernel 4a: edge messages + mean  (thread = (point, h-channel))
//   block = 256 threads = 16 points x 16 channels
// ============================================================
__global__ void __launch_bounds__(256)
feats_kernel(const float* __restrict__ We, const float* __restrict__ be)
{
    __shared__ float sWd[16 * 16];     // We_top - We_bot (applied to x_i)
    __shared__ float sWb[16 * 16];     // We_bot          (applied to x_j)
    __shared__ float sbe[16];
    __shared__ float sxi[16 * 16];     // this block's 16 point vectors
    __shared__ int   sj[16 * KNN];     // neighbor ids
    __shared__ float sxj[16 * KNN * 16]; // neighbor vectors (8KB)

    const int t  = threadIdx.x;
    const int i0 = blockIdx.x * 16;

    {
        float top = We[t];            // rows 0..15
        float bot = We[256 + t];      // rows 16..31
        sWd[t] = top - bot;
        sWb[t] = bot;
    }
    if (t < 16) sbe[t] = be[t];
    sxi[t] = g_x[i0 * 16 + t];
    if (t < 16 * KNN) sj[t] = g_idx[i0 * KNN + t];
    __syncthreads();

    // stage neighbor rows: 128 rows x 4 float4
    {
        const float4* gx4 = (const float4*)g_x;
        float4* sxj4 = (float4*)sxj;
        #pragma unroll
        for (int u = t; u < 16 * KNN * 4; u += 256) {
            int row = u >> 2, seg = u & 3;
            sxj4[u] = gx4[sj[row] * 4 + seg];
        }
    }
    __syncthreads();

    const int p = t >> 4;      // point in block
    const int h = t & 15;      // output channel
    const int i = i0 + p;

    float pre = sbe[h];
    #pragma unroll
    for (int d = 0; d < 16; ++d) pre = fmaf(sxi[p * 16 + d], sWd[d * 16 + h], pre);

    float fsum = 0.0f;
    #pragma unroll
    for (int k = 0; k < KNN; ++k) {
        const float* xj = sxj + (p * KNN + k) * 16;
        float m = pre;
        #pragma unroll
        for (int d = 0; d < 16; ++d) m = fmaf(xj[d], sWb[d * 16 + h], m);
        fsum += silu_fast(m);
    }

    g_feats[i * 16 + h] = fsum * 0.125f;
}

// ============================================================
// Kernel 4b: final MLP + concat output
// ============================================================
__global__ void __launch_bounds__(256)
out_kernel(const float* __restrict__ xp,
           const float* __restrict__ Wf1, const float* __restrict__ bf1,
           const float* __restrict__ Wf2, const float* __restrict__ bf2,
           float* __restrict__ out)
{
    __shared__ float sWf1[16 * 32], sbf1[32];
    __shared__ float sWf2[32 * 16], sbf2[16];

    int t = threadIdx.x;
    for (int u = t; u < 16 * 32; u += 256) sWf1[u] = Wf1[u];
    for (int u = t; u < 32;      u += 256) sbf1[u] = bf1[u];
    for (int u = t; u < 32 * 16; u += 256) sWf2[u] = Wf2[u];
    for (int u = t; u < 16;      u += 256) sbf2[u] = bf2[u];
    __syncthreads();

    int i = blockIdx.x * 256 + t;
    if (i >= N) return;

    float feats[16];
    const float4* gf4 = (const float4*)g_feats;
    #pragma unroll
    for (int s = 0; s < 4; ++s) {
        float4 v = gf4[i * 4 + s];
        feats[4*s+0] = v.x; feats[4*s+1] = v.y; feats[4*s+2] = v.z; feats[4*s+3] = v.w;
    }

    float f1[32];
    #pragma unroll
    for (int h = 0; h < 32; ++h) {
        float a = sbf1[h];
        #pragma unroll
        for (int d = 0; d < 16; ++d) a = fmaf(feats[d], sWf1[d * 32 + h], a);
        f1[h] = silu_fast(a);
    }
    float f2[16];
    #pragma unroll
    for (int h = 0; h < 16; ++h) {
        float a = sbf2[h];
        #pragma unroll
        for (int d = 0; d < 32; ++d) a = fmaf(f1[d], sWf2[d * 16 + h], a);
        f2[h] = a;
    }

    float* o = out + i * (16 + DIN);
    #pragma unroll
    for (int h = 0; h < 16; ++h) o[h] = f2[h];
    #pragma unroll
    for (int d = 0; d < DIN; ++d) o[16 + d] = xp[i * DIN + d];
}

// ============================================================
extern "C" void kernel_launch(void* const* d_in, const int* in_sizes, int n_in,
                              void* d_out, int out_size)
{
    const float* xp  = (const float*)d_in[0];
    const float* W1  = (const float*)d_in[1];
    const float* b1  = (const float*)d_in[2];
    const float* W2  = (const float*)d_in[3];
    const float* b2  = (const float*)d_in[4];
    const float* W3  = (const float*)d_in[5];
    const float* b3  = (const float*)d_in[6];
    const float* We  = (const float*)d_in[7];
    const float* be  = (const float*)d_in[8];
    const float* Wf1 = (const float*)d_in[9];
    const float* bf1 = (const float*)d_in[10];
    const float* Wf2 = (const float*)d_in[11];
    const float* bf2 = (const float*)d_in[12];
    float* out = (float*)d_out;

    mlp_kernel<<<N / 256, 256>>>(xp, W1, b1, W2, b2, W3, b3);
    knn_kernel<<<(N / QPB) * JSPLIT, KTHREADS>>>();
    merge_kernel<<<N / 256, 256>>>();
    feats_kernel<<<N / 16, 256>>>(We, be);
    out_kernel<<<N / 256, 256>>>(xp, Wf1, bf1, Wf2, bf2, out);
}